// round 5
// baseline (speedup 1.0000x reference)
#include <cuda_runtime.h>
#include <cuda_fp16.h>
#include <cstdint>

#define NUM_USER  200000
#define NUM_GROUP 50000
#define NROWS     (NUM_USER + NUM_GROUP)   // 250000
#define EDGES     4000000
#define DD        64
#define BB        8192
#define DEGB      1024                     // degree buckets

__device__ __forceinline__ int h2_as_int(__half2 h) {
    return *reinterpret_cast<int*>(&h);
}

// ---- scratch (__device__ globals; no cudaMalloc allowed) -------------------
__device__ __half g_e0[(size_t)NROWS * DD];   // fp16 concat(tables)
__device__ __half g_e1[(size_t)NROWS * DD];
__device__ __half g_e2[(size_t)NROWS * DD];
__device__ __half g_e3[(size_t)NROWS * DD];
__device__ int2   g_pairs[EDGES];             // (col, val-bits) sorted by row
__device__ int    g_counts[NROWS];
__device__ int    g_row_ptr[NROWS + 1];
__device__ int    g_cursor[NROWS];
__device__ int4   g_rowinfo[NROWS];           // {row, start, end, 0}, deg-desc order

__device__ int    g_degcnt[DEGB];
__device__ int    g_degcur[DEGB];
__device__ int    g_s1done;

#define SCAN_ELEMS 2048
#define NBLK_SCAN  ((NROWS + SCAN_ELEMS - 1) / SCAN_ELEMS)   // 123
__device__ int   g_blocksums[NBLK_SCAN];
__device__ int   g_blockoff [NBLK_SCAN];

// ---------------------------------------------------------------------------
// 0a) zero counters (counts, degree buckets, ticket)
__global__ __launch_bounds__(256)
void zero_kernel()
{
    int i = blockIdx.x * blockDim.x + threadIdx.x;
    if (i < NROWS) g_counts[i] = 0;
    if (i < DEGB)  g_degcnt[i] = 0;
    if (i == 0)    g_s1done = 0;
}

// 0b) fp32 tables -> fp16 concat buffer
__global__ __launch_bounds__(256)
void convert_kernel(const float4* __restrict__ ut, const float4* __restrict__ gt)
{
    int i = blockIdx.x * blockDim.x + threadIdx.x;   // one int4 (8 halves)
    if (i >= NROWS * 8) return;
    const int USER8 = NUM_USER * 8;
    float4 lo, hi;
    if (i < USER8) { lo = ut[(size_t)i * 2]; hi = ut[(size_t)i * 2 + 1]; }
    else { size_t j = i - USER8; lo = gt[j * 2]; hi = gt[j * 2 + 1]; }
    int4 o;
    o.x = h2_as_int(__floats2half2_rn(lo.x, lo.y));
    o.y = h2_as_int(__floats2half2_rn(lo.z, lo.w));
    o.z = h2_as_int(__floats2half2_rn(hi.x, hi.y));
    o.w = h2_as_int(__floats2half2_rn(hi.z, hi.w));
    reinterpret_cast<int4*>(g_e0)[i] = o;
}

// ---------------------------------------------------------------------------
// 1) histogram rows
__global__ __launch_bounds__(256)
void hist_kernel(const int4* __restrict__ rows4)
{
    int i = blockIdx.x * blockDim.x + threadIdx.x;
    if (i >= EDGES / 4) return;
    int4 r = rows4[i];
    atomicAdd(&g_counts[r.x], 1);
    atomicAdd(&g_counts[r.y], 1);
    atomicAdd(&g_counts[r.z], 1);
    atomicAdd(&g_counts[r.w], 1);
}

// ---------------------------------------------------------------------------
// 2a) per-block sums + (last block) scan of block sums
__global__ __launch_bounds__(256)
void scan1_kernel()
{
    __shared__ int sh[256];
    __shared__ int sh_last;
    int tid  = threadIdx.x;
    int base = blockIdx.x * SCAN_ELEMS + tid * 8;
    int s = 0;
    #pragma unroll
    for (int j = 0; j < 8; j++) {
        int i = base + j;
        s += (i < NROWS) ? g_counts[i] : 0;
    }
    sh[tid] = s;
    __syncthreads();
    for (int off = 128; off > 0; off >>= 1) {
        if (tid < off) sh[tid] += sh[tid + off];
        __syncthreads();
    }
    if (tid == 0) {
        g_blocksums[blockIdx.x] = sh[0];
        __threadfence();
        int t = atomicAdd(&g_s1done, 1);
        sh_last = (t == gridDim.x - 1);
    }
    __syncthreads();
    if (sh_last) {
        // scan 123 block sums with 128 threads
        __shared__ int sc[128];
        if (tid < 128) {
            int v = (tid < NBLK_SCAN) ? g_blocksums[tid] : 0;
            sc[tid] = v;
            __syncwarp();
            __syncthreads();
            for (int off = 1; off < 128; off <<= 1) {
                int t2 = (tid >= off) ? sc[tid - off] : 0;
                __syncthreads();
                sc[tid] += t2;
                __syncthreads();
            }
            if (tid < NBLK_SCAN) g_blockoff[tid] = sc[tid] - v;
        }
    }
}

// 2b) intra-block exclusive scan + offset -> row_ptr & cursor
__global__ __launch_bounds__(256)
void scan3_kernel()
{
    __shared__ int sh[256];
    int tid  = threadIdx.x;
    int base = blockIdx.x * SCAN_ELEMS + tid * 8;
    int v[8];
    int s = 0;
    #pragma unroll
    for (int j = 0; j < 8; j++) {
        int i = base + j;
        v[j] = (i < NROWS) ? g_counts[i] : 0;
        s += v[j];
    }
    sh[tid] = s;
    __syncthreads();
    for (int off = 1; off < 256; off <<= 1) {
        int t = (tid >= off) ? sh[tid - off] : 0;
        __syncthreads();
        sh[tid] += t;
        __syncthreads();
    }
    int excl = sh[tid] - s;
    int run  = g_blockoff[blockIdx.x] + excl;
    #pragma unroll
    for (int j = 0; j < 8; j++) {
        int i = base + j;
        if (i < NROWS) { g_row_ptr[i] = run; g_cursor[i] = run; }
        run += v[j];
    }
    if (blockIdx.x == 0 && tid == 0) g_row_ptr[NROWS] = EDGES;
}

// ---------------------------------------------------------------------------
// 3) degree histogram (warp-aggregated atomics)
__global__ __launch_bounds__(256)
void deghist_kernel()
{
    int r = blockIdx.x * blockDim.x + threadIdx.x;
    unsigned active = __ballot_sync(0xffffffffu, r < NROWS);
    if (r >= NROWS) return;
    int deg = g_counts[r];
    int b   = (deg < DEGB) ? deg : (DEGB - 1);
    unsigned m = __match_any_sync(active, b);
    int lane   = threadIdx.x & 31;
    int leader = __ffs(m) - 1;
    if (lane == leader) atomicAdd(&g_degcnt[b], __popc(m));
}

// 4) scan degree buckets -> descending-degree offsets (+ cursors)
__global__ __launch_bounds__(256)
void degscan_kernel()
{
    __shared__ int sh[256];
    __shared__ int sh_total;
    int tid = threadIdx.x;
    int4 c = reinterpret_cast<int4*>(g_degcnt)[tid];  // buckets 4t..4t+3
    int s = c.x + c.y + c.z + c.w;
    sh[tid] = s;
    __syncthreads();
    for (int off = 1; off < 256; off <<= 1) {
        int t = (tid >= off) ? sh[tid - off] : 0;
        __syncthreads();
        sh[tid] += t;
        __syncthreads();
    }
    if (tid == 255) sh_total = sh[255];
    __syncthreads();
    int total = sh_total;
    int excl  = sh[tid] - s;
    // inclusive per bucket, then start = total - incl  (descending degree)
    int i0 = excl + c.x;
    int i1 = i0 + c.y;
    int i2 = i1 + c.z;
    int i3 = i2 + c.w;
    int4 off4 = make_int4(total - i0, total - i1, total - i2, total - i3);
    reinterpret_cast<int4*>(g_degcur)[tid] = off4;
}

// 5) scatter rows into degree-descending rowinfo (warp-aggregated cursors)
__global__ __launch_bounds__(256)
void rowinfo_kernel()
{
    int r = blockIdx.x * blockDim.x + threadIdx.x;
    unsigned active = __ballot_sync(0xffffffffu, r < NROWS);
    if (r >= NROWS) return;
    int p0  = g_row_ptr[r];
    int p1  = g_row_ptr[r + 1];
    int deg = p1 - p0;
    int b   = (deg < DEGB) ? deg : (DEGB - 1);
    unsigned m = __match_any_sync(active, b);
    int lane   = threadIdx.x & 31;
    int leader = __ffs(m) - 1;
    int base = 0;
    if (lane == leader) base = atomicAdd(&g_degcur[b], __popc(m));
    base = __shfl_sync(m, base, leader);
    int rank = __popc(m & ((1u << lane) - 1));
    g_rowinfo[base + rank] = make_int4(r, p0, p1, 0);
}

// ---------------------------------------------------------------------------
// 6) scatter edges into row-sorted order
__global__ __launch_bounds__(256)
void scatter_kernel(const int* __restrict__ rows, const int* __restrict__ cols,
                    const float* __restrict__ vals)
{
    int e = blockIdx.x * blockDim.x + threadIdx.x;
    if (e >= EDGES) return;
    int r   = rows[e];
    int pos = atomicAdd(&g_cursor[r], 1);
    g_pairs[pos] = make_int2(cols[e], __float_as_int(vals[e]));
}

// ---------------------------------------------------------------------------
// 7) CSR spmm, fp16 storage / fp32 accumulate, degree-balanced rows.
//    8 threads per row; each owns 8 halves (one int4). Unroll 4.
// ---------------------------------------------------------------------------
__device__ __forceinline__ void acc_fma8(float* a, int4 x, float v)
{
    __half2* h = reinterpret_cast<__half2*>(&x);
    #pragma unroll
    for (int i = 0; i < 4; i++) {
        float2 f = __half22float2(h[i]);
        a[2*i]   = fmaf(v, f.x, a[2*i]);
        a[2*i+1] = fmaf(v, f.y, a[2*i+1]);
    }
}

__global__ __launch_bounds__(256)
void spmm_csr_h_kernel(const int4* __restrict__ src, int4* __restrict__ dst)
{
    int t    = blockIdx.x * blockDim.x + threadIdx.x;
    int i    = t >> 3;
    int lane = t & 7;
    if (i >= NROWS) return;

    int4 info = __ldg(&g_rowinfo[i]);
    int r  = info.x;
    int p  = info.y;
    int pe = info.z;

    float a[8];
    #pragma unroll
    for (int k = 0; k < 8; k++) a[k] = 0.f;

    // align p to even pair index for int4 (2-edge) loads
    if ((p & 1) && p < pe) {
        int2 q = __ldg(&g_pairs[p]);
        int4 x = __ldg(&src[(size_t)q.x * 8 + lane]);
        acc_fma8(a, x, __int_as_float(q.y));
        p++;
    }
    const int4* pairs4 = reinterpret_cast<const int4*>(g_pairs);
    for (; p + 4 <= pe; p += 4) {
        int4 q01 = __ldg(&pairs4[p >> 1]);
        int4 q23 = __ldg(&pairs4[(p >> 1) + 1]);
        int4 x0 = __ldg(&src[(size_t)q01.x * 8 + lane]);
        int4 x1 = __ldg(&src[(size_t)q01.z * 8 + lane]);
        int4 x2 = __ldg(&src[(size_t)q23.x * 8 + lane]);
        int4 x3 = __ldg(&src[(size_t)q23.z * 8 + lane]);
        acc_fma8(a, x0, __int_as_float(q01.y));
        acc_fma8(a, x1, __int_as_float(q01.w));
        acc_fma8(a, x2, __int_as_float(q23.y));
        acc_fma8(a, x3, __int_as_float(q23.w));
    }
    if (p + 2 <= pe) {
        int4 q01 = __ldg(&pairs4[p >> 1]);
        int4 x0 = __ldg(&src[(size_t)q01.x * 8 + lane]);
        int4 x1 = __ldg(&src[(size_t)q01.z * 8 + lane]);
        acc_fma8(a, x0, __int_as_float(q01.y));
        acc_fma8(a, x1, __int_as_float(q01.w));
        p += 2;
    }
    if (p < pe) {
        int2 q = __ldg(&g_pairs[p]);
        int4 x = __ldg(&src[(size_t)q.x * 8 + lane]);
        acc_fma8(a, x, __int_as_float(q.y));
    }

    int4 o;
    o.x = h2_as_int(__floats2half2_rn(a[0], a[1]));
    o.y = h2_as_int(__floats2half2_rn(a[2], a[3]));
    o.z = h2_as_int(__floats2half2_rn(a[4], a[5]));
    o.w = h2_as_int(__floats2half2_rn(a[6], a[7]));
    dst[(size_t)r * 8 + lane] = o;
}

// ---------------------------------------------------------------------------
// 8) final six-way gather: (emb0 + e1 + e2 + e3)/4 on the fly
// ---------------------------------------------------------------------------
__device__ __forceinline__ float4 load_h4(const __half* base, size_t row, int lane)
{
    uint2 u = __ldg(reinterpret_cast<const uint2*>(base + row * DD) + lane);
    __half2 h0 = *reinterpret_cast<__half2*>(&u.x);
    __half2 h1 = *reinterpret_cast<__half2*>(&u.y);
    float2 f0 = __half22float2(h0);
    float2 f1 = __half22float2(h1);
    return make_float4(f0.x, f0.y, f1.x, f1.y);
}

__global__ __launch_bounds__(256)
void gather_kernel(const float4* __restrict__ ut, const float4* __restrict__ gt,
                   const int* __restrict__ ui, const int* __restrict__ pg,
                   const int* __restrict__ ng, float4* __restrict__ out)
{
    int t = blockIdx.x * blockDim.x + threadIdx.x;
    if (t >= BB * 16) return;
    int b    = t >> 4;
    int lane = t & 15;

    int u = ui[b];
    size_t gp = (size_t)NUM_USER + pg[b];
    size_t gn = (size_t)NUM_USER + ng[b];

    const float s = 0.25f;

    {
        float4 t0 = ut[(size_t)u * 16 + lane];
        float4 f1 = load_h4(g_e1, (size_t)u, lane);
        float4 f2 = load_h4(g_e2, (size_t)u, lane);
        float4 f3 = load_h4(g_e3, (size_t)u, lane);
        out[((size_t)0 * BB + b) * 16 + lane] = make_float4(
            (t0.x + f1.x + f2.x + f3.x) * s, (t0.y + f1.y + f2.y + f3.y) * s,
            (t0.z + f1.z + f2.z + f3.z) * s, (t0.w + f1.w + f2.w + f3.w) * s);
        out[((size_t)3 * BB + b) * 16 + lane] = t0;
    }
    {
        float4 t0 = gt[(gp - NUM_USER) * 16 + lane];
        float4 f1 = load_h4(g_e1, gp, lane);
        float4 f2 = load_h4(g_e2, gp, lane);
        float4 f3 = load_h4(g_e3, gp, lane);
        out[((size_t)1 * BB + b) * 16 + lane] = make_float4(
            (t0.x + f1.x + f2.x + f3.x) * s, (t0.y + f1.y + f2.y + f3.y) * s,
            (t0.z + f1.z + f2.z + f3.z) * s, (t0.w + f1.w + f2.w + f3.w) * s);
        out[((size_t)4 * BB + b) * 16 + lane] = t0;
    }
    {
        float4 t0 = gt[(gn - NUM_USER) * 16 + lane];
        float4 f1 = load_h4(g_e1, gn, lane);
        float4 f2 = load_h4(g_e2, gn, lane);
        float4 f3 = load_h4(g_e3, gn, lane);
        out[((size_t)2 * BB + b) * 16 + lane] = make_float4(
            (t0.x + f1.x + f2.x + f3.x) * s, (t0.y + f1.y + f2.y + f3.y) * s,
            (t0.z + f1.z + f2.z + f3.z) * s, (t0.w + f1.w + f2.w + f3.w) * s);
        out[((size_t)5 * BB + b) * 16 + lane] = t0;
    }
}

// ---------------------------------------------------------------------------
extern "C" void kernel_launch(void* const* d_in, const int* in_sizes, int n_in,
                              void* d_out, int out_size)
{
    const float* user_table  = (const float*)d_in[0];
    const float* group_table = (const float*)d_in[1];
    const float* adj_vals    = (const float*)d_in[2];
    const int*   rows        = (const int*)  d_in[3];
    const int*   cols        = (const int*)  d_in[4];
    const int*   user_inputs = (const int*)  d_in[5];
    const int*   pos_groups  = (const int*)  d_in[6];
    const int*   neg_groups  = (const int*)  d_in[7];

    __half* e0 = nullptr, * e1 = nullptr, * e2 = nullptr, * e3 = nullptr;
    cudaGetSymbolAddress((void**)&e0, g_e0);
    cudaGetSymbolAddress((void**)&e1, g_e1);
    cudaGetSymbolAddress((void**)&e2, g_e2);
    cudaGetSymbolAddress((void**)&e3, g_e3);

    const int TB = 256;

    zero_kernel<<<(NROWS + TB - 1) / TB, TB>>>();
    convert_kernel<<<(NROWS * 8 + TB - 1) / TB, TB>>>(
        (const float4*)user_table, (const float4*)group_table);

    // CSR build (counting sort by row)
    hist_kernel<<<(EDGES / 4 + TB - 1) / TB, TB>>>((const int4*)rows);
    scan1_kernel<<<NBLK_SCAN, TB>>>();
    scan3_kernel<<<NBLK_SCAN, TB>>>();

    // degree-descending row schedule
    deghist_kernel<<<(NROWS + TB - 1) / TB, TB>>>();
    degscan_kernel<<<1, 256>>>();
    rowinfo_kernel<<<(NROWS + TB - 1) / TB, TB>>>();

    scatter_kernel<<<(EDGES + TB - 1) / TB, TB>>>(rows, cols, adj_vals);

    const int grid_spmm = (NROWS * 8 + TB - 1) / TB;   // 7813

    spmm_csr_h_kernel<<<grid_spmm, TB>>>((const int4*)e0, (int4*)e1);
    spmm_csr_h_kernel<<<grid_spmm, TB>>>((const int4*)e1, (int4*)e2);
    spmm_csr_h_kernel<<<grid_spmm, TB>>>((const int4*)e2, (int4*)e3);

    gather_kernel<<<(BB * 16 + TB - 1) / TB, TB>>>(
        (const float4*)user_table, (const float4*)group_table,
        user_inputs, pos_groups, neg_groups, (float4*)d_out);
}

// round 6
// speedup vs baseline: 1.0359x; 1.0359x over previous
#include <cuda_runtime.h>
#include <cuda_fp16.h>
#include <cstdint>

#define NUM_USER  200000
#define NUM_GROUP 50000
#define NROWS     (NUM_USER + NUM_GROUP)   // 250000
#define EDGES     4000000
#define DD        64
#define BB        8192

__device__ __forceinline__ int h2_as_int(__half2 h) {
    return *reinterpret_cast<int*>(&h);
}

// ---- scratch (__device__ globals; no cudaMalloc allowed) -------------------
__device__ __half g_e0[(size_t)NROWS * DD];   // fp16 concat(tables)
__device__ __half g_e1[(size_t)NROWS * DD];
__device__ __half g_e2[(size_t)NROWS * DD];
__device__ __half g_e3[(size_t)NROWS * DD];
__device__ int2   g_pairs[EDGES];             // (col, val-bits) sorted by row
__device__ int    g_counts[NROWS];
__device__ int    g_row_ptr[NROWS + 1];
__device__ int    g_cursor[NROWS];
__device__ int    g_s1done;

#define SCAN_ELEMS 2048
#define NBLK_SCAN  ((NROWS + SCAN_ELEMS - 1) / SCAN_ELEMS)   // 123
__device__ int   g_blocksums[NBLK_SCAN];
__device__ int   g_blockoff [NBLK_SCAN];

// ---------------------------------------------------------------------------
// 0) convert fp32 tables -> fp16 concat buffer; zero histogram + ticket
// ---------------------------------------------------------------------------
__global__ __launch_bounds__(256)
void convert_kernel(const float4* __restrict__ ut, const float4* __restrict__ gt)
{
    int i = blockIdx.x * blockDim.x + threadIdx.x;   // one int4 (8 halves)
    if (i < NROWS) g_counts[i] = 0;
    if (i == 0)    g_s1done = 0;
    if (i >= NROWS * 8) return;
    const int USER8 = NUM_USER * 8;
    float4 lo, hi;
    if (i < USER8) { lo = ut[(size_t)i * 2]; hi = ut[(size_t)i * 2 + 1]; }
    else { size_t j = i - USER8; lo = gt[j * 2]; hi = gt[j * 2 + 1]; }
    int4 o;
    o.x = h2_as_int(__floats2half2_rn(lo.x, lo.y));
    o.y = h2_as_int(__floats2half2_rn(lo.z, lo.w));
    o.z = h2_as_int(__floats2half2_rn(hi.x, hi.y));
    o.w = h2_as_int(__floats2half2_rn(hi.z, hi.w));
    reinterpret_cast<int4*>(g_e0)[i] = o;
}

// ---------------------------------------------------------------------------
// 1) histogram rows (int4-vectorized read)
// ---------------------------------------------------------------------------
__global__ __launch_bounds__(256)
void hist_kernel(const int4* __restrict__ rows4)
{
    int i = blockIdx.x * blockDim.x + threadIdx.x;
    if (i >= EDGES / 4) return;
    int4 r = rows4[i];
    atomicAdd(&g_counts[r.x], 1);
    atomicAdd(&g_counts[r.y], 1);
    atomicAdd(&g_counts[r.z], 1);
    atomicAdd(&g_counts[r.w], 1);
}

// ---------------------------------------------------------------------------
// 2a) per-block sums + (last block via ticket) scan of the 123 block sums
// ---------------------------------------------------------------------------
__global__ __launch_bounds__(256)
void scan1_kernel()
{
    __shared__ int sh[256];
    __shared__ int sh_last;
    int tid  = threadIdx.x;
    int base = blockIdx.x * SCAN_ELEMS + tid * 8;
    int s = 0;
    #pragma unroll
    for (int j = 0; j < 8; j++) {
        int i = base + j;
        s += (i < NROWS) ? g_counts[i] : 0;
    }
    sh[tid] = s;
    __syncthreads();
    for (int off = 128; off > 0; off >>= 1) {
        if (tid < off) sh[tid] += sh[tid + off];
        __syncthreads();
    }
    if (tid == 0) {
        g_blocksums[blockIdx.x] = sh[0];
        __threadfence();
        int t = atomicAdd(&g_s1done, 1);
        sh_last = (t == gridDim.x - 1);
    }
    __syncthreads();
    if (sh_last) {
        __shared__ int sc[128];
        if (tid < 128) {
            int v = (tid < NBLK_SCAN) ? g_blocksums[tid] : 0;
            sc[tid] = v;
            __syncthreads();
            for (int off = 1; off < 128; off <<= 1) {
                int t2 = (tid >= off) ? sc[tid - off] : 0;
                __syncthreads();
                sc[tid] += t2;
                __syncthreads();
            }
            if (tid < NBLK_SCAN) g_blockoff[tid] = sc[tid] - v;
        }
    }
}

// 2b) intra-block exclusive scan + offset -> row_ptr & cursor
__global__ __launch_bounds__(256)
void scan3_kernel()
{
    __shared__ int sh[256];
    int tid  = threadIdx.x;
    int base = blockIdx.x * SCAN_ELEMS + tid * 8;
    int v[8];
    int s = 0;
    #pragma unroll
    for (int j = 0; j < 8; j++) {
        int i = base + j;
        v[j] = (i < NROWS) ? g_counts[i] : 0;
        s += v[j];
    }
    sh[tid] = s;
    __syncthreads();
    for (int off = 1; off < 256; off <<= 1) {
        int t = (tid >= off) ? sh[tid - off] : 0;
        __syncthreads();
        sh[tid] += t;
        __syncthreads();
    }
    int excl = sh[tid] - s;
    int run  = g_blockoff[blockIdx.x] + excl;
    #pragma unroll
    for (int j = 0; j < 8; j++) {
        int i = base + j;
        if (i < NROWS) { g_row_ptr[i] = run; g_cursor[i] = run; }
        run += v[j];
    }
    if (blockIdx.x == 0 && tid == 0) g_row_ptr[NROWS] = EDGES;
}

// ---------------------------------------------------------------------------
// 3) scatter edges into row-sorted order (4 edges/thread, int4 reads)
// ---------------------------------------------------------------------------
__global__ __launch_bounds__(256)
void scatter_kernel(const int4* __restrict__ rows4, const int4* __restrict__ cols4,
                    const float4* __restrict__ vals4)
{
    int i = blockIdx.x * blockDim.x + threadIdx.x;
    if (i >= EDGES / 4) return;
    int4   r = rows4[i];
    int4   c = cols4[i];
    float4 v = vals4[i];
    int p0 = atomicAdd(&g_cursor[r.x], 1);
    g_pairs[p0] = make_int2(c.x, __float_as_int(v.x));
    int p1 = atomicAdd(&g_cursor[r.y], 1);
    g_pairs[p1] = make_int2(c.y, __float_as_int(v.y));
    int p2 = atomicAdd(&g_cursor[r.z], 1);
    g_pairs[p2] = make_int2(c.z, __float_as_int(v.z));
    int p3 = atomicAdd(&g_cursor[r.w], 1);
    g_pairs[p3] = make_int2(c.w, __float_as_int(v.w));
}

// ---------------------------------------------------------------------------
// 4) CSR spmm, fp16 storage / fp32 accumulation, row-ordered (locality!).
//    8 threads per row; each owns 8 halves (one int4). int4 pair loads, unroll 4.
// ---------------------------------------------------------------------------
__device__ __forceinline__ void acc_fma8(float* a, int4 x, float v)
{
    __half2* h = reinterpret_cast<__half2*>(&x);
    #pragma unroll
    for (int i = 0; i < 4; i++) {
        float2 f = __half22float2(h[i]);
        a[2*i]   = fmaf(v, f.x, a[2*i]);
        a[2*i+1] = fmaf(v, f.y, a[2*i+1]);
    }
}

__global__ __launch_bounds__(256)
void spmm_csr_h_kernel(const int4* __restrict__ src, int4* __restrict__ dst)
{
    int t    = blockIdx.x * blockDim.x + threadIdx.x;
    int r    = t >> 3;
    int lane = t & 7;
    if (r >= NROWS) return;

    int p  = __ldg(&g_row_ptr[r]);
    int pe = __ldg(&g_row_ptr[r + 1]);

    float a[8];
    #pragma unroll
    for (int k = 0; k < 8; k++) a[k] = 0.f;

    // align p to even pair index for int4 (2-edge) loads
    if ((p & 1) && p < pe) {
        int2 q = __ldg(&g_pairs[p]);
        int4 x = __ldg(&src[(size_t)q.x * 8 + lane]);
        acc_fma8(a, x, __int_as_float(q.y));
        p++;
    }
    const int4* pairs4 = reinterpret_cast<const int4*>(g_pairs);
    for (; p + 4 <= pe; p += 4) {
        int4 q01 = __ldg(&pairs4[p >> 1]);
        int4 q23 = __ldg(&pairs4[(p >> 1) + 1]);
        int4 x0 = __ldg(&src[(size_t)q01.x * 8 + lane]);
        int4 x1 = __ldg(&src[(size_t)q01.z * 8 + lane]);
        int4 x2 = __ldg(&src[(size_t)q23.x * 8 + lane]);
        int4 x3 = __ldg(&src[(size_t)q23.z * 8 + lane]);
        acc_fma8(a, x0, __int_as_float(q01.y));
        acc_fma8(a, x1, __int_as_float(q01.w));
        acc_fma8(a, x2, __int_as_float(q23.y));
        acc_fma8(a, x3, __int_as_float(q23.w));
    }
    if (p + 2 <= pe) {
        int4 q01 = __ldg(&pairs4[p >> 1]);
        int4 x0 = __ldg(&src[(size_t)q01.x * 8 + lane]);
        int4 x1 = __ldg(&src[(size_t)q01.z * 8 + lane]);
        acc_fma8(a, x0, __int_as_float(q01.y));
        acc_fma8(a, x1, __int_as_float(q01.w));
        p += 2;
    }
    if (p < pe) {
        int2 q = __ldg(&g_pairs[p]);
        int4 x = __ldg(&src[(size_t)q.x * 8 + lane]);
        acc_fma8(a, x, __int_as_float(q.y));
    }

    int4 o;
    o.x = h2_as_int(__floats2half2_rn(a[0], a[1]));
    o.y = h2_as_int(__floats2half2_rn(a[2], a[3]));
    o.z = h2_as_int(__floats2half2_rn(a[4], a[5]));
    o.w = h2_as_int(__floats2half2_rn(a[6], a[7]));
    dst[(size_t)r * 8 + lane] = o;
}

// ---------------------------------------------------------------------------
// 5) final six-way gather: (emb0 + e1 + e2 + e3)/4 on the fly
// ---------------------------------------------------------------------------
__device__ __forceinline__ float4 load_h4(const __half* base, size_t row, int lane)
{
    uint2 u = __ldg(reinterpret_cast<const uint2*>(base + row * DD) + lane);
    __half2 h0 = *reinterpret_cast<__half2*>(&u.x);
    __half2 h1 = *reinterpret_cast<__half2*>(&u.y);
    float2 f0 = __half22float2(h0);
    float2 f1 = __half22float2(h1);
    return make_float4(f0.x, f0.y, f1.x, f1.y);
}

__global__ __launch_bounds__(256)
void gather_kernel(const float4* __restrict__ ut, const float4* __restrict__ gt,
                   const int* __restrict__ ui, const int* __restrict__ pg,
                   const int* __restrict__ ng, float4* __restrict__ out)
{
    int t = blockIdx.x * blockDim.x + threadIdx.x;
    if (t >= BB * 16) return;
    int b    = t >> 4;
    int lane = t & 15;

    int u = ui[b];
    size_t gp = (size_t)NUM_USER + pg[b];
    size_t gn = (size_t)NUM_USER + ng[b];

    const float s = 0.25f;

    {
        float4 t0 = ut[(size_t)u * 16 + lane];
        float4 f1 = load_h4(g_e1, (size_t)u, lane);
        float4 f2 = load_h4(g_e2, (size_t)u, lane);
        float4 f3 = load_h4(g_e3, (size_t)u, lane);
        out[((size_t)0 * BB + b) * 16 + lane] = make_float4(
            (t0.x + f1.x + f2.x + f3.x) * s, (t0.y + f1.y + f2.y + f3.y) * s,
            (t0.z + f1.z + f2.z + f3.z) * s, (t0.w + f1.w + f2.w + f3.w) * s);
        out[((size_t)3 * BB + b) * 16 + lane] = t0;
    }
    {
        float4 t0 = gt[(gp - NUM_USER) * 16 + lane];
        float4 f1 = load_h4(g_e1, gp, lane);
        float4 f2 = load_h4(g_e2, gp, lane);
        float4 f3 = load_h4(g_e3, gp, lane);
        out[((size_t)1 * BB + b) * 16 + lane] = make_float4(
            (t0.x + f1.x + f2.x + f3.x) * s, (t0.y + f1.y + f2.y + f3.y) * s,
            (t0.z + f1.z + f2.z + f3.z) * s, (t0.w + f1.w + f2.w + f3.w) * s);
        out[((size_t)4 * BB + b) * 16 + lane] = t0;
    }
    {
        float4 t0 = gt[(gn - NUM_USER) * 16 + lane];
        float4 f1 = load_h4(g_e1, gn, lane);
        float4 f2 = load_h4(g_e2, gn, lane);
        float4 f3 = load_h4(g_e3, gn, lane);
        out[((size_t)2 * BB + b) * 16 + lane] = make_float4(
            (t0.x + f1.x + f2.x + f3.x) * s, (t0.y + f1.y + f2.y + f3.y) * s,
            (t0.z + f1.z + f2.z + f3.z) * s, (t0.w + f1.w + f2.w + f3.w) * s);
        out[((size_t)5 * BB + b) * 16 + lane] = t0;
    }
}

// ---------------------------------------------------------------------------
extern "C" void kernel_launch(void* const* d_in, const int* in_sizes, int n_in,
                              void* d_out, int out_size)
{
    const float* user_table  = (const float*)d_in[0];
    const float* group_table = (const float*)d_in[1];
    const float* adj_vals    = (const float*)d_in[2];
    const int*   rows        = (const int*)  d_in[3];
    const int*   cols        = (const int*)  d_in[4];
    const int*   user_inputs = (const int*)  d_in[5];
    const int*   pos_groups  = (const int*)  d_in[6];
    const int*   neg_groups  = (const int*)  d_in[7];

    __half* e0 = nullptr, * e1 = nullptr, * e2 = nullptr, * e3 = nullptr;
    cudaGetSymbolAddress((void**)&e0, g_e0);
    cudaGetSymbolAddress((void**)&e1, g_e1);
    cudaGetSymbolAddress((void**)&e2, g_e2);
    cudaGetSymbolAddress((void**)&e3, g_e3);

    const int TB = 256;

    convert_kernel<<<(NROWS * 8 + TB - 1) / TB, TB>>>(
        (const float4*)user_table, (const float4*)group_table);

    hist_kernel<<<(EDGES / 4 + TB - 1) / TB, TB>>>((const int4*)rows);
    scan1_kernel<<<NBLK_SCAN, TB>>>();
    scan3_kernel<<<NBLK_SCAN, TB>>>();
    scatter_kernel<<<(EDGES / 4 + TB - 1) / TB, TB>>>(
        (const int4*)rows, (const int4*)cols, (const float4*)adj_vals);

    const int grid_spmm = (NROWS * 8 + TB - 1) / TB;   // 7813

    spmm_csr_h_kernel<<<grid_spmm, TB>>>((const int4*)e0, (int4*)e1);
    spmm_csr_h_kernel<<<grid_spmm, TB>>>((const int4*)e1, (int4*)e2);
    spmm_csr_h_kernel<<<grid_spmm, TB>>>((const int4*)e2, (int4*)e3);

    gather_kernel<<<(BB * 16 + TB - 1) / TB, TB>>>(
        (const float4*)user_table, (const float4*)group_table,
        user_inputs, pos_groups, neg_groups, (float4*)d_out);
}